// round 1
// baseline (speedup 1.0000x reference)
#include <cuda_runtime.h>
#include <math.h>

#define NB 64
#define NL 64
#define ND 512

// Scratch (device globals: allocation-free rule)
__device__ float g_G[NB * NL * NL];   // Gram per j: g_G[j*4096 + s1*64 + s2]
__device__ float g_w1[NB * NL];       // ||sent[i,q]||
__device__ float g_sim[NB * NB];      // sim matrix (post-transpose layout): g_sim[a*64+b]

// ---------------------------------------------------------------------------
// Kernel 1: per-j Gram matrix G_j = ecg_j @ ecg_j^T  (64x64x512),
//           plus w1 row norms of sent (block j handles sent index j).
// ---------------------------------------------------------------------------
__global__ __launch_bounds__(256) void gram_kernel(const float* __restrict__ ecg,
                                                   const float* __restrict__ sent) {
    __shared__ float sA[NL * 33];
    const int j = blockIdx.x;
    const int tid = threadIdx.x;
    const int tx = tid & 15, ty = tid >> 4;
    const int row0 = ty * 4, col0 = tx * 4;
    const float* base = ecg + (size_t)j * NL * ND;

    float c[4][4];
#pragma unroll
    for (int m = 0; m < 4; m++)
#pragma unroll
        for (int n = 0; n < 4; n++) c[m][n] = 0.f;

    const int lq = tid >> 3;          // 0..31
    const int lf = (tid & 7) * 4;     // 0..28

    for (int kt = 0; kt < ND; kt += 32) {
        __syncthreads();
#pragma unroll
        for (int r = 0; r < 2; r++) {
            int q = lq + r * 32;
            float4 v = *reinterpret_cast<const float4*>(base + q * ND + kt + lf);
            sA[q * 33 + lf + 0] = v.x;
            sA[q * 33 + lf + 1] = v.y;
            sA[q * 33 + lf + 2] = v.z;
            sA[q * 33 + lf + 3] = v.w;
        }
        __syncthreads();
#pragma unroll
        for (int k = 0; k < 32; k++) {
            float a[4], b[4];
#pragma unroll
            for (int m = 0; m < 4; m++) a[m] = sA[(row0 + m) * 33 + k];
#pragma unroll
            for (int n = 0; n < 4; n++) b[n] = sA[(col0 + n) * 33 + k];
#pragma unroll
            for (int m = 0; m < 4; m++)
#pragma unroll
                for (int n = 0; n < 4; n++) c[m][n] = fmaf(a[m], b[n], c[m][n]);
        }
    }

    float* Gp = g_G + (size_t)j * NL * NL;
#pragma unroll
    for (int m = 0; m < 4; m++)
#pragma unroll
        for (int n = 0; n < 4; n++) Gp[(row0 + m) * NL + col0 + n] = c[m][n];

    // w1: ||sent[j, q]|| ; 4 threads per q, 128 elements each
    {
        int q = tid >> 2;
        int p = tid & 3;
        const float* sp = sent + (size_t)j * NL * ND + q * ND + p * 128;
        float s = 0.f;
#pragma unroll 8
        for (int t2 = 0; t2 < 32; t2++) {
            float4 v = *reinterpret_cast<const float4*>(sp + t2 * 4);
            s = fmaf(v.x, v.x, fmaf(v.y, v.y, fmaf(v.z, v.z, fmaf(v.w, v.w, s))));
        }
        s += __shfl_xor_sync(0xffffffffu, s, 1);
        s += __shfl_xor_sync(0xffffffffu, s, 2);
        if (p == 0) g_w1[j * NL + q] = sqrtf(s);
    }
}

// ---------------------------------------------------------------------------
// Kernel 2: one CTA per (i, j) pair.
//   S[q][s] = sent[i,q] . ecg[j,s]                 (64x64x512 fp32 GEMM)
//   A1[s,q] = softmax_q S[q,s]  ->  V[q][s] = 4*A1[s,q]
//   A2[q][s] = softmax_s V[q][s]                   (this is attn[i,j,q,s])
//   w12[q] = sum_s A2*S   (registers)
//   w2^2[q] = A2_q G_j A2_q^T  via  T = A2 @ G_j   (64x64x64 GEMM)
//   sim[j,i] = 10*log(sum_q exp(5*cos))
//   if i==j: att_maps output = A2
// ---------------------------------------------------------------------------
__global__ __launch_bounds__(256) void pair_kernel(const float* __restrict__ ecg,
                                                   const float* __restrict__ sent,
                                                   float* __restrict__ out) {
    __shared__ float region0[4224];       // GEMM1 tiles (2x 64*33), then Ah[64*66]
    __shared__ float Gh[64 * 65];
    __shared__ float pbuf[16 * 68];
    __shared__ float colm[64], crZ[64], rowm[64], rrZ[64], esum[64];

    float* sA = region0;
    float* sB = region0 + 2112;
    float* Ah = region0;

    const int i = blockIdx.x, j = blockIdx.y;
    const int tid = threadIdx.x;
    const int tx = tid & 15, ty = tid >> 4;
    const int row0 = ty * 4, col0 = tx * 4;

    const float* Sp = sent + (size_t)i * NL * ND;
    const float* Ep = ecg + (size_t)j * NL * ND;

    float c[4][4];
#pragma unroll
    for (int m = 0; m < 4; m++)
#pragma unroll
        for (int n = 0; n < 4; n++) c[m][n] = 0.f;

    const int lq = tid >> 3;
    const int lf = (tid & 7) * 4;

    // ---- GEMM 1: S = sent_i @ ecg_j^T ----
    for (int kt = 0; kt < ND; kt += 32) {
        __syncthreads();
#pragma unroll
        for (int r = 0; r < 2; r++) {
            int q = lq + r * 32;
            float4 va = *reinterpret_cast<const float4*>(Sp + q * ND + kt + lf);
            sA[q * 33 + lf + 0] = va.x;
            sA[q * 33 + lf + 1] = va.y;
            sA[q * 33 + lf + 2] = va.z;
            sA[q * 33 + lf + 3] = va.w;
            float4 vb = *reinterpret_cast<const float4*>(Ep + q * ND + kt + lf);
            sB[q * 33 + lf + 0] = vb.x;
            sB[q * 33 + lf + 1] = vb.y;
            sB[q * 33 + lf + 2] = vb.z;
            sB[q * 33 + lf + 3] = vb.w;
        }
        __syncthreads();
#pragma unroll
        for (int k = 0; k < 32; k++) {
            float a[4], b[4];
#pragma unroll
            for (int m = 0; m < 4; m++) a[m] = sA[(row0 + m) * 33 + k];
#pragma unroll
            for (int n = 0; n < 4; n++) b[n] = sB[(col0 + n) * 33 + k];
#pragma unroll
            for (int m = 0; m < 4; m++)
#pragma unroll
                for (int n = 0; n < 4; n++) c[m][n] = fmaf(a[m], b[n], c[m][n]);
        }
    }
    __syncthreads();

    // ---- Softmax 1 (over q, per column s): column max ----
    {
        float pm[4];
#pragma unroll
        for (int n = 0; n < 4; n++) {
            pm[n] = c[0][n];
#pragma unroll
            for (int m = 1; m < 4; m++) pm[n] = fmaxf(pm[n], c[m][n]);
            pbuf[ty * 68 + col0 + n] = pm[n];
        }
    }
    __syncthreads();
    if (tid < 64) {
        float m = -1e30f;
#pragma unroll
        for (int p = 0; p < 16; p++) m = fmaxf(m, pbuf[p * 68 + tid]);
        colm[tid] = m;
    }
    __syncthreads();
    // column sum of exp
    {
#pragma unroll
        for (int n = 0; n < 4; n++) {
            float s = 0.f;
#pragma unroll
            for (int m = 0; m < 4; m++) s += __expf(c[m][n] - colm[col0 + n]);
            pbuf[ty * 68 + col0 + n] = s;
        }
    }
    __syncthreads();
    if (tid < 64) {
        float z = 0.f;
#pragma unroll
        for (int p = 0; p < 16; p++) z += pbuf[p * 68 + tid];
        crZ[tid] = 1.f / z;
    }
    __syncthreads();

    // ---- V[q][s] = 4 * A1[s,q] ; row (q) softmax stats ----
    float v[4][4];
#pragma unroll
    for (int m = 0; m < 4; m++)
#pragma unroll
        for (int n = 0; n < 4; n++)
            v[m][n] = 4.f * __expf(c[m][n] - colm[col0 + n]) * crZ[col0 + n];

#pragma unroll
    for (int m = 0; m < 4; m++) {
        float pm = v[m][0];
#pragma unroll
        for (int n = 1; n < 4; n++) pm = fmaxf(pm, v[m][n]);
        pbuf[tx * 68 + row0 + m] = pm;
    }
    __syncthreads();
    if (tid < 64) {
        float m = -1e30f;
#pragma unroll
        for (int p = 0; p < 16; p++) m = fmaxf(m, pbuf[p * 68 + tid]);
        rowm[tid] = m;
    }
    __syncthreads();
#pragma unroll
    for (int m = 0; m < 4; m++) {
        float s = 0.f;
#pragma unroll
        for (int n = 0; n < 4; n++) s += __expf(v[m][n] - rowm[row0 + m]);
        pbuf[tx * 68 + row0 + m] = s;
    }
    __syncthreads();
    if (tid < 64) {
        float z = 0.f;
#pragma unroll
        for (int p = 0; p < 16; p++) z += pbuf[p * 68 + tid];
        rrZ[tid] = 1.f / z;
    }
    __syncthreads();

    // ---- A2 (final attn) in regs; w12 partials ----
#pragma unroll
    for (int m = 0; m < 4; m++) {
        float w12p = 0.f;
#pragma unroll
        for (int n = 0; n < 4; n++) {
            float a2 = __expf(v[m][n] - rowm[row0 + m]) * rrZ[row0 + m];
            v[m][n] = a2;
            w12p = fmaf(a2, c[m][n], w12p);
        }
        pbuf[tx * 68 + row0 + m] = w12p;
    }
    __syncthreads();

    float my_w12 = 0.f;   // valid for tid < 64 (row q = tid)
    if (tid < 64) {
#pragma unroll
        for (int p = 0; p < 16; p++) my_w12 += pbuf[p * 68 + tid];
    }

    // ---- Stage A2 -> Ah (region0 reuse: GEMM1 tiles dead), load G_j -> Gh ----
#pragma unroll
    for (int m = 0; m < 4; m++)
#pragma unroll
        for (int n = 0; n < 4; n++) Ah[(row0 + m) * 66 + col0 + n] = v[m][n];
    {
        const float* Gp = g_G + (size_t)j * NL * NL;
        int f = (tid & 15) * 4;
        int q0 = tid >> 4;
#pragma unroll
        for (int r = 0; r < 4; r++) {
            int q = q0 + r * 16;
            float4 g = *reinterpret_cast<const float4*>(Gp + q * NL + f);
            Gh[q * 65 + f + 0] = g.x;
            Gh[q * 65 + f + 1] = g.y;
            Gh[q * 65 + f + 2] = g.z;
            Gh[q * 65 + f + 3] = g.w;
        }
    }
    __syncthreads();

    // ---- GEMM 2: T = A2 @ G_j ; then w2^2 partials = sum T*A2 ----
    float t4[4][4];
#pragma unroll
    for (int m = 0; m < 4; m++)
#pragma unroll
        for (int n = 0; n < 4; n++) t4[m][n] = 0.f;
#pragma unroll 8
    for (int k = 0; k < 64; k++) {
        float a[4], g[4];
#pragma unroll
        for (int m = 0; m < 4; m++) a[m] = Ah[(row0 + m) * 66 + k];
#pragma unroll
        for (int n = 0; n < 4; n++) g[n] = Gh[k * 65 + col0 + n];
#pragma unroll
        for (int m = 0; m < 4; m++)
#pragma unroll
            for (int n = 0; n < 4; n++) t4[m][n] = fmaf(a[m], g[n], t4[m][n]);
    }
    __syncthreads();
#pragma unroll
    for (int m = 0; m < 4; m++) {
        float w2p = 0.f;
#pragma unroll
        for (int n = 0; n < 4; n++) w2p = fmaf(t4[m][n], v[m][n], w2p);
        pbuf[tx * 68 + row0 + m] = w2p;
    }
    __syncthreads();

    // ---- cos, exp(5 cos), pair reduction -> sim[j,i] ----
    if (tid < 64) {
        float w2sq = 0.f;
#pragma unroll
        for (int p = 0; p < 16; p++) w2sq += pbuf[p * 68 + tid];
        float w2 = sqrtf(fmaxf(w2sq, 0.f));
        float den = fmaxf(g_w1[i * NL + tid] * w2, 1e-8f);
        float cs = my_w12 / den;
        esum[tid] = __expf(5.f * cs);
    }
    __syncthreads();
    if (tid == 0) {
        float z = 0.f;
#pragma unroll
        for (int q = 0; q < 64; q++) z += esum[q];
        g_sim[j * NB + i] = 10.f * logf(z);
    }

    // ---- att_maps output on the diagonal ----
    if (i == j) {
        float* ap = out + 1 + (size_t)i * NL * NL;
#pragma unroll
        for (int m = 0; m < 4; m++)
#pragma unroll
            for (int n = 0; n < 4; n++)
                ap[(row0 + m) * NL + col0 + n] = v[m][n];
    }
}

// ---------------------------------------------------------------------------
// Kernel 3: symmetric InfoNCE loss from the 64x64 sim matrix.
// ---------------------------------------------------------------------------
__global__ void loss_kernel(float* __restrict__ out) {
    __shared__ float sh[64];
    int t = threadIdx.x;  // 64 threads
    float m1 = -1e30f, m2 = -1e30f;
    for (int b = 0; b < NB; b++) {
        m1 = fmaxf(m1, g_sim[t * NB + b]);
        m2 = fmaxf(m2, g_sim[b * NB + t]);
    }
    float z1 = 0.f, z2 = 0.f;
    for (int b = 0; b < NB; b++) {
        z1 += __expf(g_sim[t * NB + b] - m1);
        z2 += __expf(g_sim[b * NB + t] - m2);
    }
    float dg = g_sim[t * NB + t];
    sh[t] = (dg - (m1 + logf(z1))) + (dg - (m2 + logf(z2)));
    __syncthreads();
    if (t == 0) {
        float s = 0.f;
        for (int q = 0; q < NB; q++) s += sh[q];
        out[0] = -s / (2.f * (float)NB);
    }
}

extern "C" void kernel_launch(void* const* d_in, const int* in_sizes, int n_in,
                              void* d_out, int out_size) {
    const float* ecg = (const float*)d_in[0];   // ecg_embs (64,64,512)
    const float* sent = (const float*)d_in[1];  // sent_embs (64,64,512)
    float* out = (float*)d_out;                 // [loss, att_maps(64,1,64,1,64)]

    gram_kernel<<<NB, 256>>>(ecg, sent);
    dim3 grid(NB, NB);
    pair_kernel<<<grid, 256>>>(ecg, sent, out);
    loss_kernel<<<1, 64>>>(out);
}

// round 3
// speedup vs baseline: 1.0897x; 1.0897x over previous
#include <cuda_runtime.h>
#include <math.h>
#include <cstdint>

#define NB 64
#define NL 64
#define ND 512

// ---------------- device scratch (allocation-free rule) ----------------
__device__ float g_G[NB * NL * NL];     // Gram per j
__device__ float g_w1[NB * NL];         // ||sent[i,q]||
__device__ float g_sim[NB * NB];        // g_sim[j*64+i] = sim[i][j]... (see pair_kernel)
__device__ float g_S[4096u * 4096u];    // scores: row = sent flat (i*64+q), col = ecg flat (j*64+s)

// ---------------- helpers ----------------
__device__ __forceinline__ uint32_t smem_u32(const void* p) {
    uint32_t a;
    asm("{ .reg .u64 t; cvta.to.shared.u64 t, %1; cvt.u32.u64 %0, t; }" : "=r"(a) : "l"(p));
    return a;
}
__device__ __forceinline__ float tf32r(float x) {
    float r;
    asm("cvt.rna.tf32.f32 %0, %1;" : "=f"(r) : "f"(x));
    return r;
}
__device__ __forceinline__ void lds64(uint32_t& x, uint32_t& y, uint32_t a) {
    asm volatile("ld.shared.v2.b32 {%0, %1}, [%2];" : "=r"(x), "=r"(y) : "r"(a));
}
__device__ __forceinline__ void sts64(uint32_t a, float x, float y) {
    asm volatile("st.shared.v2.f32 [%0], {%1, %2};" :: "r"(a), "f"(x), "f"(y) : "memory");
}
__device__ __forceinline__ void mma_tf32(float* c, const uint32_t* a, const uint32_t* b) {
    asm volatile(
        "mma.sync.aligned.m16n8k8.row.col.f32.tf32.tf32.f32 "
        "{%0,%1,%2,%3}, {%4,%5,%6,%7}, {%8,%9}, {%0,%1,%2,%3};"
        : "+f"(c[0]), "+f"(c[1]), "+f"(c[2]), "+f"(c[3])
        : "r"(a[0]), "r"(a[1]), "r"(a[2]), "r"(a[3]), "r"(b[0]), "r"(b[1]));
}

// ===========================================================================
// Kernel A: S = sent(4096x512) @ ecg(4096x512)^T via 3xTF32 mma.sync
//   CTA tile 128x128, 8 warps (2M x 4N), warp tile 64x32 (m16n8k8 frags 4x4).
//   Smem rows stride 40 words; cols interleaved (c&3)*2+(c>>2) per 8-group so
//   fragment reads {a0,a2},{a1,a3},{b0,b1} are LDS.64 and conflict-free.
// ===========================================================================
#define BK 32
#define NCH (ND / BK)
#define ROWW 40u                       // words per smem row
#define TILE_WORDS (128u * ROWW)       // 5120 words = 20480 B
#define OFF_AHI 0u
#define OFF_ALO (TILE_WORDS * 4u)
#define OFF_BHI (TILE_WORDS * 8u)
#define OFF_BLO (TILE_WORDS * 12u)
#define STAGE_B (TILE_WORDS * 16u)     // 81920 B per stage
#define SMEM_TOTAL (2u * STAGE_B)      // 163840 B

__global__ __launch_bounds__(256, 1) void s_gemm_kernel(const float* __restrict__ ecg,
                                                        const float* __restrict__ sent) {
    extern __shared__ char dsm[];
    const uint32_t sbase = smem_u32(dsm);

    const int tid = threadIdx.x;
    const int wid = tid >> 5, lane = tid & 31;
    const int tileN = blockIdx.x;   // 0..31
    const int tileM = blockIdx.y;   // 0..31

    // global load mapping: row = tid/2, 16 consecutive cols at (tid&1)*16
    const int grow = tid >> 1;
    const int gcb = (tid & 1) * 16;
    const float* Ag = sent + ((size_t)tileM * 128 + grow) * ND + gcb;
    const float* Bg = ecg + ((size_t)tileN * 128 + grow) * ND + gcb;

    // smem store addresses (byte) for the 16 values: two 8-col groups
    // value c (0..15) -> abs col cc = gcb + c; word = row*40 + (cc>>3)*8 + (cc&3)*2 + ((cc&7)>>2)
    // pairs (d, d+4) within a group are adjacent words -> sts64
    uint32_t stsw[8];  // word offsets for pair d of group g2 (g2*4 + d)
#pragma unroll
    for (int g2 = 0; g2 < 2; ++g2)
#pragma unroll
        for (int d = 0; d < 4; ++d)
            stsw[g2 * 4 + d] = (uint32_t)grow * ROWW + (uint32_t)(((gcb >> 3) + g2) * 8 + 2 * d);

    // warp tile
    const uint32_t warpM = (uint32_t)(wid & 1) * 64u;
    const uint32_t warpN = (uint32_t)(wid >> 1) * 32u;
    const uint32_t lg = lane >> 2, lt = lane & 3;

    float acc[4][4][4];
#pragma unroll
    for (int mi = 0; mi < 4; ++mi)
#pragma unroll
        for (int ni = 0; ni < 4; ++ni)
#pragma unroll
            for (int r = 0; r < 4; ++r) acc[mi][ni][r] = 0.f;

    float4 ra[4], rb[4];
#pragma unroll
    for (int r = 0; r < 4; ++r) {
        ra[r] = *reinterpret_cast<const float4*>(Ag + r * 4);
        rb[r] = *reinterpret_cast<const float4*>(Bg + r * 4);
    }

    // ---- STS one chunk from ra/rb ----
    auto sts_chunk = [&](uint32_t st) {
        float v[16];
#pragma unroll
        for (int r = 0; r < 4; ++r) {
            v[r * 4 + 0] = ra[r].x; v[r * 4 + 1] = ra[r].y;
            v[r * 4 + 2] = ra[r].z; v[r * 4 + 3] = ra[r].w;
        }
#pragma unroll
        for (int p = 0; p < 8; ++p) {
            int g2 = p >> 2, d = p & 3;
            float x = v[g2 * 8 + d], y = v[g2 * 8 + d + 4];
            float hx = tf32r(x), hy = tf32r(y);
            uint32_t a = st + stsw[p] * 4u;
            sts64(a + OFF_AHI, hx, hy);
            sts64(a + OFF_ALO, tf32r(x - hx), tf32r(y - hy));
        }
#pragma unroll
        for (int r = 0; r < 4; ++r) {
            v[r * 4 + 0] = rb[r].x; v[r * 4 + 1] = rb[r].y;
            v[r * 4 + 2] = rb[r].z; v[r * 4 + 3] = rb[r].w;
        }
#pragma unroll
        for (int p = 0; p < 8; ++p) {
            int g2 = p >> 2, d = p & 3;
            float x = v[g2 * 8 + d], y = v[g2 * 8 + d + 4];
            float hx = tf32r(x), hy = tf32r(y);
            uint32_t a = st + stsw[p] * 4u;
            sts64(a + OFF_BHI, hx, hy);
            sts64(a + OFF_BLO, tf32r(x - hx), tf32r(y - hy));
        }
    };

    sts_chunk(sbase);
    __syncthreads();

    for (int t = 0; t < NCH; ++t) {
        const uint32_t st = sbase + (uint32_t)(t & 1) * STAGE_B;
        if (t + 1 < NCH) {
#pragma unroll
            for (int r = 0; r < 4; ++r) {
                ra[r] = *reinterpret_cast<const float4*>(Ag + (t + 1) * BK + r * 4);
                rb[r] = *reinterpret_cast<const float4*>(Bg + (t + 1) * BK + r * 4);
            }
        }
        // ---- MMA over this chunk: 4 k-steps ----
#pragma unroll
        for (int k8 = 0; k8 < 4; ++k8) {
            uint32_t ah[4][4], al[4][4], bh[4][2], bl[4][2];
            const uint32_t kw = (uint32_t)k8 * 8u + 2u * lt;
#pragma unroll
            for (int mi = 0; mi < 4; ++mi) {
                uint32_t r0 = (warpM + mi * 16u + lg) * ROWW + kw;
                uint32_t r1 = r0 + 8u * ROWW;
                lds64(ah[mi][0], ah[mi][2], st + OFF_AHI + r0 * 4u);
                lds64(ah[mi][1], ah[mi][3], st + OFF_AHI + r1 * 4u);
                lds64(al[mi][0], al[mi][2], st + OFF_ALO + r0 * 4u);
                lds64(al[mi][1], al[mi][3], st + OFF_ALO + r1 * 4u);
            }
#pragma unroll
            for (int ni = 0; ni < 4; ++ni) {
                uint32_t r0 = (warpN + ni * 8u + lg) * ROWW + kw;
                lds64(bh[ni][0], bh[ni][1], st + OFF_BHI + r0 * 4u);
                lds64(bl[ni][0], bl[ni][1], st + OFF_BLO + r0 * 4u);
            }
#pragma unroll
            for (int mi = 0; mi < 4; ++mi)
#pragma unroll
                for (int ni = 0; ni < 4; ++ni) {
                    mma_tf32(acc[mi][ni], ah[mi], bh[ni]);
                    mma_tf32(acc[mi][ni], ah[mi], bl[ni]);
                    mma_tf32(acc[mi][ni], al[mi], bh[ni]);
                }
        }
        if (t + 1 < NCH) sts_chunk(sbase + (uint32_t)((t + 1) & 1) * STAGE_B);
        __syncthreads();
    }

    // ---- epilogue: write C to g_S ----
    const size_t rbase = (size_t)tileM * 128 + warpM + lg;
    const size_t cbase = (size_t)tileN * 128 + warpN + lt * 2;
#pragma unroll
    for (int mi = 0; mi < 4; ++mi)
#pragma unroll
        for (int ni = 0; ni < 4; ++ni) {
            float* p0 = g_S + (rbase + mi * 16) * 4096u + cbase + ni * 8;
            *reinterpret_cast<float2*>(p0) = make_float2(acc[mi][ni][0], acc[mi][ni][1]);
            *reinterpret_cast<float2*>(p0 + 8 * 4096u) = make_float2(acc[mi][ni][2], acc[mi][ni][3]);
        }
}

// ===========================================================================
// Kernel B: Gram quadrants (256 CTAs) + w1 norms.
// ===========================================================================
__global__ __launch_bounds__(256) void gram_kernel(const float* __restrict__ ecg,
                                                   const float* __restrict__ sent) {
    __shared__ float sA[32 * 66];
    __shared__ float sB[32 * 66];
    const int j = blockIdx.x >> 2;
    const int quad = blockIdx.x & 3;
    const int qr = (quad >> 1) * 32, qc = (quad & 1) * 32;
    const int tid = threadIdx.x;
    const int tx = tid & 15, ty = tid >> 4;
    const int r0 = ty * 2, c0 = tx * 2;
    const float* base = ecg + (size_t)j * NL * ND;

    float c00 = 0.f, c01 = 0.f, c10 = 0.f, c11 = 0.f;
    const int lrow = tid >> 3;
    const int lcol = (tid & 7) * 8;

    for (int kt = 0; kt < ND; kt += 64) {
        __syncthreads();
#pragma unroll
        for (int r = 0; r < 2; ++r) {
            float4 va = *reinterpret_cast<const float4*>(base + (qr + lrow) * ND + kt + lcol + r * 4);
            sA[lrow * 66 + lcol + r * 4 + 0] = va.x;
            sA[lrow * 66 + lcol + r * 4 + 1] = va.y;
            sA[lrow * 66 + lcol + r * 4 + 2] = va.z;
            sA[lrow * 66 + lcol + r * 4 + 3] = va.w;
            float4 vb = *reinterpret_cast<const float4*>(base + (qc + lrow) * ND + kt + lcol + r * 4);
            sB[lrow * 66 + lcol + r * 4 + 0] = vb.x;
            sB[lrow * 66 + lcol + r * 4 + 1] = vb.y;
            sB[lrow * 66 + lcol + r * 4 + 2] = vb.z;
            sB[lrow * 66 + lcol + r * 4 + 3] = vb.w;
        }
        __syncthreads();
#pragma unroll 8
        for (int k = 0; k < 64; ++k) {
            float a0 = sA[r0 * 66 + k], a1 = sA[(r0 + 1) * 66 + k];
            float b0 = sB[c0 * 66 + k], b1 = sB[(c0 + 1) * 66 + k];
            c00 = fmaf(a0, b0, c00);
            c01 = fmaf(a0, b1, c01);
            c10 = fmaf(a1, b0, c10);
            c11 = fmaf(a1, b1, c11);
        }
    }
    float* Gp = g_G + (size_t)j * NL * NL;
    Gp[(qr + r0) * NL + qc + c0] = c00;
    Gp[(qr + r0) * NL + qc + c0 + 1] = c01;
    Gp[(qr + r0 + 1) * NL + qc + c0] = c10;
    Gp[(qr + r0 + 1) * NL + qc + c0 + 1] = c11;

    if (quad == 0) {
        int q = tid >> 2;
        int p = tid & 3;
        const float* sp = sent + (size_t)j * NL * ND + q * ND + p * 128;
        float s = 0.f;
#pragma unroll 8
        for (int t2 = 0; t2 < 32; t2++) {
            float4 v = *reinterpret_cast<const float4*>(sp + t2 * 4);
            s = fmaf(v.x, v.x, fmaf(v.y, v.y, fmaf(v.z, v.z, fmaf(v.w, v.w, s))));
        }
        s += __shfl_xor_sync(0xffffffffu, s, 1);
        s += __shfl_xor_sync(0xffffffffu, s, 2);
        if (p == 0) g_w1[j * NL + q] = sqrtf(s);
    }
}

// ===========================================================================
// Kernel C: per-pair epilogue (softmaxes, w12, Gram quadratic form, sim)
// ===========================================================================
__global__ __launch_bounds__(256) void pair_kernel(float* __restrict__ out) {
    __shared__ float Ah[64 * 66];
    __shared__ float Gh[64 * 65];
    __shared__ float pbuf[16 * 68];
    __shared__ float colm[64], crZ[64], rowm[64], rrZ[64], esum[64];

    const int i = blockIdx.x, j = blockIdx.y;
    const int tid = threadIdx.x;
    const int tx = tid & 15, ty = tid >> 4;
    const int row0 = ty * 4, col0 = tx * 4;

    float c[4][4];
    const float* Sp = g_S + ((size_t)i * 64) * 4096u + (size_t)j * 64;
#pragma unroll
    for (int m = 0; m < 4; m++) {
        float4 v = *reinterpret_cast<const float4*>(Sp + (size_t)(row0 + m) * 4096u + col0);
        c[m][0] = v.x; c[m][1] = v.y; c[m][2] = v.z; c[m][3] = v.w;
    }
    {
        const float* Gp = g_G + (size_t)j * NL * NL;
        int f = (tid & 15) * 4;
        int q0 = tid >> 4;
#pragma unroll
        for (int r = 0; r < 4; ++r) {
            int q = q0 + r * 16;
            float4 g = *reinterpret_cast<const float4*>(Gp + q * NL + f);
            Gh[q * 65 + f + 0] = g.x;
            Gh[q * 65 + f + 1] = g.y;
            Gh[q * 65 + f + 2] = g.z;
            Gh[q * 65 + f + 3] = g.w;
        }
    }

    // softmax over q (per column s)
#pragma unroll
    for (int n = 0; n < 4; n++) {
        float pm = c[0][n];
#pragma unroll
        for (int m = 1; m < 4; m++) pm = fmaxf(pm, c[m][n]);
        pbuf[ty * 68 + col0 + n] = pm;
    }
    __syncthreads();
    if (tid < 64) {
        float m = -1e30f;
#pragma unroll
        for (int p = 0; p < 16; p++) m = fmaxf(m, pbuf[p * 68 + tid]);
        colm[tid] = m;
    }
    __syncthreads();
#pragma unroll
    for (int n = 0; n < 4; n++) {
        float s = 0.f;
#pragma unroll
        for (int m = 0; m < 4; m++) s += __expf(c[m][n] - colm[col0 + n]);
        pbuf[ty * 68 + col0 + n] = s;
    }
    __syncthreads();
    if (tid < 64) {
        float z = 0.f;
#pragma unroll
        for (int p = 0; p < 16; p++) z += pbuf[p * 68 + tid];
        crZ[tid] = 1.f / z;
    }
    __syncthreads();

    // V = 4*A1^T ; row softmax
    float v[4][4];
#pragma unroll
    for (int m = 0; m < 4; m++)
#pragma unroll
        for (int n = 0; n < 4; n++)
            v[m][n] = 4.f * __expf(c[m][n] - colm[col0 + n]) * crZ[col0 + n];

#pragma unroll
    for (int m = 0; m < 4; m++) {
        float pm = v[m][0];
#pragma unroll
        for (int n = 1; n < 4; n++) pm = fmaxf(pm, v[m][n]);
        pbuf[tx * 68 + row0 + m] = pm;
    }
    __syncthreads();
    if (tid < 64) {
        float m = -1e30f;
#pragma unroll
        for (int p = 0; p < 16; p++) m = fmaxf(m, pbuf[p * 68 + tid]);
        rowm[tid] = m;
    }
    __syncthreads();
#pragma unroll
    for (int m = 0; m < 4; m++) {
        float s = 0.f;
#pragma unroll
        for (int n = 0; n < 4; n++) s += __expf(v[m][n] - rowm[row0 + m]);
        pbuf[tx * 68 + row0 + m] = s;
    }
    __syncthreads();
    if (tid < 64) {
        float z = 0.f;
#pragma unroll
        for (int p = 0; p < 16; p++) z += pbuf[p * 68 + tid];
        rrZ[tid] = 1.f / z;
    }
    __syncthreads();

    // A2 + w12 partials
#pragma unroll
    for (int m = 0; m < 4; m++) {
        float w12p = 0.f;
#pragma unroll
        for (int n = 0; n < 4; n++) {
            float a2 = __expf(v[m][n] - rowm[row0 + m]) * rrZ[row0 + m];
            v[m][n] = a2;
            w12p = fmaf(a2, c[m][n], w12p);
        }
        pbuf[tx * 68 + row0 + m] = w12p;
    }
    __syncthreads();
    float my_w12 = 0.f;
    if (tid < 64) {
#pragma unroll
        for (int p = 0; p < 16; p++) my_w12 += pbuf[p * 68 + tid];
    }

#pragma unroll
    for (int m = 0; m < 4; m++)
#pragma unroll
        for (int n = 0; n < 4; n++) Ah[(row0 + m) * 66 + col0 + n] = v[m][n];
    __syncthreads();

    // GEMM2: T = A2 @ G_j ; w2^2 partials
    float t4[4][4];
#pragma unroll
    for (int m = 0; m < 4; m++)
#pragma unroll
        for (int n = 0; n < 4; n++) t4[m][n] = 0.f;
#pragma unroll 8
    for (int k = 0; k < 64; k++) {
        float a[4], g[4];
#pragma unroll
        for (int m = 0; m < 4; m++) a[m] = Ah[(row0 + m) * 66 + k];
#pragma unroll
        for (int n = 0; n < 4; n++) g[n] = Gh[k * 65 + col0 + n];
#pragma unroll
        for (int m = 0; m < 4; m++)
#pragma unroll
            for (int n = 0; n < 4; n++) t4[m][n] = fmaf(a[m], g[n], t4[m][n]);
    }
    __syncthreads();
#pragma unroll
    for (int m = 0; m < 4; m++) {
        float w2p = 0.f;
#pragma unroll
        for (int n = 0; n < 4; n++) w2p = fmaf(t4[m][n], v[m][n], w2p);
        pbuf[tx * 68 + row0 + m] = w2p;
    }
    __syncthreads();

    if (tid < 64) {
        float w2sq = 0.f;
#pragma unroll
        for (int p = 0; p < 16; p++) w2sq += pbuf[p * 68 + tid];
        float w2 = sqrtf(fmaxf(w2sq, 0.f));
        float den = fmaxf(g_w1[i * NL + tid] * w2, 1e-8f);
        float cs = my_w12 / den;
        esum[tid] = __expf(5.f * cs);
    }
    __syncthreads();
    if (tid == 0) {
        float z = 0.f;
#pragma unroll
        for (int q = 0; q < 64; q++) z += esum[q];
        g_sim[j * NB + i] = 10.f * logf(z);
    }

    if (i == j) {
        float* ap = out + 1 + (size_t)i * NL * NL;
#pragma unroll
        for (int m = 0; m < 4; m++)
#pragma unroll
            for (int n = 0; n < 4; n++)
                ap[(row0 + m) * NL + col0 + n] = v[m][n];
    }
}

// ===========================================================================
// Kernel D: symmetric InfoNCE loss.
// ===========================================================================
__global__ void loss_kernel(float* __restrict__ out) {
    __shared__ float sh[64];
    int t = threadIdx.x;
    float m1 = -1e30f, m2 = -1e30f;
    for (int b = 0; b < NB; b++) {
        m1 = fmaxf(m1, g_sim[t * NB + b]);
        m2 = fmaxf(m2, g_sim[b * NB + t]);
    }
    float z1 = 0.f, z2 = 0.f;
    for (int b = 0; b < NB; b++) {
        z1 += __expf(g_sim[t * NB + b] - m1);
        z2 += __expf(g_sim[b * NB + t] - m2);
    }
    float dg = g_sim[t * NB + t];
    sh[t] = (dg - (m1 + logf(z1))) + (dg - (m2 + logf(z2)));
    __syncthreads();
    if (t == 0) {
        float s = 0.f;
        for (int q = 0; q < NB; q++) s += sh[q];
        out[0] = -s / (2.f * (float)NB);
    }
}

extern "C" void kernel_launch(void* const* d_in, const int* in_sizes, int n_in,
                              void* d_out, int out_size) {
    const float* ecg = (const float*)d_in[0];   // (64,64,512)
    const float* sent = (const float*)d_in[1];  // (64,64,512)
    float* out = (float*)d_out;                 // [loss, att_maps]

    cudaFuncSetAttribute(s_gemm_kernel, cudaFuncAttributeMaxDynamicSharedMemorySize, SMEM_TOTAL);

    s_gemm_kernel<<<dim3(32, 32), 256, SMEM_TOTAL>>>(ecg, sent);
    gram_kernel<<<256, 256>>>(ecg, sent);
    pair_kernel<<<dim3(64, 64), 256>>>(out);
    loss_kernel<<<1, 64>>>(out);
}